// round 5
// baseline (speedup 1.0000x reference)
#include <cuda_runtime.h>
#include <cstdint>
#include <math.h>

#define BB 32
#define SS 196
#define TT 64
#define HH 1024
#define VV 32000
#define RR 4096   // 4*H
#define PADW 8
#define NB 148    // persistent grid size

// ---------------- scratch ----------------
__device__ float g_M2[(size_t)BB*SS*HH];
__device__ float g_E [(size_t)BB*TT*RR];
__device__ float g_hs[(size_t)TT*BB*HH];   // rows = t*32+b
__device__ float g_gph[(size_t)RR*BB];     // W_hh@h partials [r][b]
__device__ float g_h [BB*HH];
__device__ float g_c [BB*HH];
__device__ float g_ctx[BB*HH];
__device__ float g_scores[BB*SS];
__device__ unsigned g_bar;

// ---------------- tf32 helpers ----------------
__device__ __forceinline__ float f2tf32(float x) {
    uint32_t u; asm("cvt.rna.tf32.f32 %0, %1;" : "=r"(u) : "f"(x));
    return __uint_as_float(u);
}
__device__ __forceinline__ void mma_op(float* c, const uint32_t* a, const uint32_t* b) {
    asm volatile(
        "mma.sync.aligned.m16n8k8.row.col.f32.tf32.tf32.f32 "
        "{%0,%1,%2,%3},{%4,%5,%6,%7},{%8,%9},{%0,%1,%2,%3};"
        : "+f"(c[0]), "+f"(c[1]), "+f"(c[2]), "+f"(c[3])
        : "r"(a[0]), "r"(a[1]), "r"(a[2]), "r"(a[3]), "r"(b[0]), "r"(b[1]));
}

// ---------------- tf32 tensor-core GEMM (unchanged from R4) ----------------
__global__ __launch_bounds__(256, 2) void mma_gemm(
    const float* __restrict__ A, const float* __restrict__ Bsrc,
    float* __restrict__ C, int M, int N, int K, int ldb,
    const int* __restrict__ gatherIdx, const float* __restrict__ gatherTab,
    const float* __restrict__ bias, int mode)
{
    __shared__ float As[16][128 + PADW];
    __shared__ float Bs[16][128 + PADW];
    int tid = threadIdx.x;
    int n0 = blockIdx.x * 128, m0 = blockIdx.y * 128;
    int warp = tid >> 5, lane = tid & 31;
    int wm = warp >> 1, wn = warp & 1;
    int grp = lane >> 2, tg = lane & 3;

    float acc[2][8][4] = {};

    const float* arow[2];
    int ac4[2];
    #pragma unroll
    for (int it = 0; it < 2; it++) {
        int idx = tid + it * 256;
        int r = idx >> 2; ac4[it] = (idx & 3) * 4;
        arow[it] = gatherIdx ? (gatherTab + (size_t)gatherIdx[m0 + r] * K)
                             : (A + (size_t)(m0 + r) * K);
    }

    for (int k0 = 0; k0 < K; k0 += 16) {
        #pragma unroll
        for (int it = 0; it < 2; it++) {
            int idx = tid + it * 256;
            int r = idx >> 2;
            float4 v = *(const float4*)(arow[it] + k0 + ac4[it]);
            As[ac4[it]+0][r] = f2tf32(v.x); As[ac4[it]+1][r] = f2tf32(v.y);
            As[ac4[it]+2][r] = f2tf32(v.z); As[ac4[it]+3][r] = f2tf32(v.w);
        }
        if (mode == 2) {
            #pragma unroll
            for (int it = 0; it < 2; it++) {
                int idx = tid + it * 256;
                int r = idx >> 5, c4 = (idx & 31) * 4;
                float4 v = *(const float4*)(Bsrc + (size_t)(k0 + r) * ldb + n0 + c4);
                Bs[r][c4+0] = f2tf32(v.x); Bs[r][c4+1] = f2tf32(v.y);
                Bs[r][c4+2] = f2tf32(v.z); Bs[r][c4+3] = f2tf32(v.w);
            }
        } else {
            #pragma unroll
            for (int it = 0; it < 2; it++) {
                int idx = tid + it * 256;
                int r = idx >> 2, c4 = (idx & 3) * 4;
                float4 v = *(const float4*)(Bsrc + (size_t)(n0 + r) * ldb + k0 + c4);
                Bs[c4+0][r] = f2tf32(v.x); Bs[c4+1][r] = f2tf32(v.y);
                Bs[c4+2][r] = f2tf32(v.z); Bs[c4+3][r] = f2tf32(v.w);
            }
        }
        __syncthreads();

        #pragma unroll
        for (int ks = 0; ks < 2; ks++) {
            int kb = ks * 8;
            uint32_t af[2][4], bf[8][2];
            #pragma unroll
            for (int mt = 0; mt < 2; mt++) {
                int r = wm * 32 + mt * 16 + grp;
                af[mt][0] = __float_as_uint(As[kb+tg  ][r  ]);
                af[mt][1] = __float_as_uint(As[kb+tg  ][r+8]);
                af[mt][2] = __float_as_uint(As[kb+tg+4][r  ]);
                af[mt][3] = __float_as_uint(As[kb+tg+4][r+8]);
            }
            #pragma unroll
            for (int nt = 0; nt < 8; nt++) {
                int cix = wn * 64 + nt * 8 + grp;
                bf[nt][0] = __float_as_uint(Bs[kb+tg  ][cix]);
                bf[nt][1] = __float_as_uint(Bs[kb+tg+4][cix]);
            }
            #pragma unroll
            for (int mt = 0; mt < 2; mt++)
                #pragma unroll
                for (int nt = 0; nt < 8; nt++)
                    mma_op(acc[mt][nt], af[mt], bf[nt]);
        }
        __syncthreads();
    }

    #pragma unroll
    for (int mt = 0; mt < 2; mt++) {
        int mg = m0 + wm * 32 + mt * 16 + grp;
        #pragma unroll
        for (int nt = 0; nt < 8; nt++) {
            int ng = n0 + wn * 64 + nt * 8 + tg * 2;
            float* a4 = acc[mt][nt];
            if (mode == 1) {
                float b0 = __ldg(bias + ng), b1 = __ldg(bias + ng + 1);
                size_t r1 = ((size_t)(mg & 31) * TT + (mg >> 5)) * N;
                size_t r2 = ((size_t)((mg+8) & 31) * TT + ((mg+8) >> 5)) * N;
                *(float2*)(C + r1 + ng) = make_float2(a4[0] + b0, a4[1] + b1);
                *(float2*)(C + r2 + ng) = make_float2(a4[2] + b0, a4[3] + b1);
            } else {
                *(float2*)(C + (size_t)mg * N + ng)       = make_float2(a4[0], a4[1]);
                *(float2*)(C + (size_t)(mg + 8) * N + ng) = make_float2(a4[2], a4[3]);
            }
        }
    }
}

// ---------------- lightweight global barrier (no CCTL.IVALL) ----------------
// Global stores are write-through to L2; mutable cross-block data is read with
// __ldcg (L1 bypass), so no L1 invalidate is needed. Release/acquire on the
// counter orders everything through L2.
__device__ __forceinline__ void gridbar(unsigned target) {
    __syncthreads();
    if (threadIdx.x == 0) {
        unsigned one = 1u, x;
        asm volatile("red.release.gpu.global.add.u32 [%0], %1;"
                     :: "l"(&g_bar), "r"(one) : "memory");
        do {
            asm volatile("ld.acquire.gpu.global.u32 %0, [%1];"
                         : "=r"(x) : "l"(&g_bar));
        } while (x < target);
    }
    __syncthreads();
}

// ---------------- persistent recurrence: 3 phases / step ----------------
// smem: smemx[32][1025] | E_s[1024] | gate_s[1024]   (139392 B)
__global__ __launch_bounds__(1024, 1) void k_recur(
    const float* __restrict__ memory,
    const float* __restrict__ W_ih, const float* __restrict__ W_hh,
    const float* __restrict__ b_ih, const float* __restrict__ b_hh)
{
    extern __shared__ float smem[];
    float* smemx  = smem;                    // [32][1025]
    float* E_s    = smem + 32 * 1025;        // 1024
    float* gate_s = E_s + 1024;              // 1024

    const int tid = threadIdx.x;
    const int bid = blockIdx.x;
    const int w = tid >> 5, lane = tid & 31;
    unsigned tgt = NB;

    for (int t = 0; t < TT; t++) {
        // ================= Phase 1: scores  +  W_hh @ h =================
        // stage h into smemx (conflict-free stride 1025)
        for (int i = tid; i < BB * HH; i += 1024)
            smemx[(i >> 10) * 1025 + (i & 1023)] = __ldcg(&g_h[i]);
        __syncthreads();

        if (w >= 14) {
            // ---- scores: warps 14..31 (18 per block) ----
            for (int p = bid * 18 + (w - 14); p < BB * SS; p += NB * 18) {
                int b = p / SS;
                const float4* m4 = (const float4*)(g_M2 + (size_t)p * HH);
                const float4* h4 = (const float4*)(g_h + b * HH);
                float a = 0.f;
                #pragma unroll
                for (int i = 0; i < 8; i++) {
                    float4 mv = m4[i * 32 + lane];
                    float4 hv = __ldcg(&h4[i * 32 + lane]);
                    a += mv.x*hv.x + mv.y*hv.y + mv.z*hv.z + mv.w*hv.w;
                }
                #pragma unroll
                for (int o = 16; o; o >>= 1) a += __shfl_xor_sync(0xffffffffu, a, o);
                if (!lane) g_scores[p] = a;
            }
        } else {
            // ---- hh-gates: warps 0..13, 2 rows each, 28 rows/block ----
            int r0 = bid * 28 + 2 * w;
            int r0c = (r0 > RR - 2) ? (RR - 2) : r0;     // clamp for safe reads
            const float* w0 = W_hh + (size_t)r0c * HH;
            const float* w1 = w0 + HH;
            const float* xr = smemx + lane * 1025;
            float acc0 = 0.f, acc1 = 0.f;
            #pragma unroll 4
            for (int k = 0; k < HH; k += 4) {
                float4 wv0 = *(const float4*)(w0 + k);
                float4 wv1 = *(const float4*)(w1 + k);
                float a0 = xr[k], a1 = xr[k+1], a2 = xr[k+2], a3 = xr[k+3];
                acc0 = fmaf(wv0.x, a0, acc0); acc0 = fmaf(wv0.y, a1, acc0);
                acc0 = fmaf(wv0.z, a2, acc0); acc0 = fmaf(wv0.w, a3, acc0);
                acc1 = fmaf(wv1.x, a0, acc1); acc1 = fmaf(wv1.y, a1, acc1);
                acc1 = fmaf(wv1.z, a2, acc1); acc1 = fmaf(wv1.w, a3, acc1);
            }
            if (r0     < RR && r0 == r0c) g_gph[(size_t)r0     * BB + lane] = acc0;
            if (r0 + 1 < RR && r0 == r0c) g_gph[(size_t)(r0+1) * BB + lane] = acc1;
        }
        gridbar(tgt); tgt += NB;

        // ================= Phase 2: softmax + ctx (128 blocks) =================
        if (bid < 128) {
            float* red  = smem;          // 256
            float* swp  = smem + 256;    // 256
            float* part = smem + 512;    // 1024
            int b = bid >> 2, jblk = bid & 3;
            float v = -1e30f;
            if (tid < 256) {
                v = (tid < SS) ? __ldcg(&g_scores[b * SS + tid]) : -1e30f;
                red[tid] = v;
            }
            __syncthreads();
            for (int o = 128; o; o >>= 1) { if (tid < o) red[tid] = fmaxf(red[tid], red[tid+o]); __syncthreads(); }
            float mx = red[0]; __syncthreads();
            float e = 0.f;
            if (tid < 256) { e = (tid < SS) ? expf(v - mx) : 0.f; red[tid] = e; }
            __syncthreads();
            for (int o = 128; o; o >>= 1) { if (tid < o) red[tid] += red[tid+o]; __syncthreads(); }
            float inv = 1.f / red[0];
            if (tid < 256) swp[tid] = e * inv;
            __syncthreads();

            int jj = tid & 255, sp = tid >> 8;
            int j = jblk * 256 + jj;
            const float* mp = memory + ((size_t)b * SS + sp * 49) * HH + j;
            float acc = 0.f;
            #pragma unroll 7
            for (int s = 0; s < 49; s++)
                acc += swp[sp * 49 + s] * mp[(size_t)s * HH];
            part[sp * 256 + jj] = acc;
            __syncthreads();
            if (tid < 256)
                g_ctx[b * HH + j] = part[jj] + part[256+jj] + part[512+jj] + part[768+jj];
        }
        gridbar(tgt); tgt += NB;

        // ================= Phase 3: ctx-gates + LSTM cell (128 blocks) =========
        if (bid < 128) {
            const int jb = bid;
            // stage ctx
            for (int i = tid; i < BB * HH; i += 1024)
                smemx[(i >> 10) * 1025 + (i & 1023)] = __ldcg(&g_ctx[i]);
            // stage E slice: tid = (b<<5)|(g<<3)|jo
            {
                int b = tid >> 5, g = (tid >> 3) & 3, jo = tid & 7;
                E_s[tid] = g_E[((size_t)b * TT + t) * RR + g * 1024 + jb * 8 + jo];
            }
            __syncthreads();

            if (w < 16) {
                int rl0 = 2 * w;                          // row-local 0..31
                int g0 = rl0 >> 3, jo0 = rl0 & 7;
                int r0 = g0 * 1024 + jb * 8 + jo0;        // r1 = r0+1 (same gate)
                const float* w0 = W_ih + (size_t)r0 * 2048 + 1024;
                const float* w1 = w0 + 2048;
                const float* xr = smemx + lane * 1025;
                float acc0 = 0.f, acc1 = 0.f;
                #pragma unroll 4
                for (int k = 0; k < HH; k += 4) {
                    float4 wv0 = *(const float4*)(w0 + k);
                    float4 wv1 = *(const float4*)(w1 + k);
                    float a0 = xr[k], a1 = xr[k+1], a2 = xr[k+2], a3 = xr[k+3];
                    acc0 = fmaf(wv0.x, a0, acc0); acc0 = fmaf(wv0.y, a1, acc0);
                    acc0 = fmaf(wv0.z, a2, acc0); acc0 = fmaf(wv0.w, a3, acc0);
                    acc1 = fmaf(wv1.x, a0, acc1); acc1 = fmaf(wv1.y, a1, acc1);
                    acc1 = fmaf(wv1.z, a2, acc1); acc1 = fmaf(wv1.w, a3, acc1);
                }
                acc0 += __ldcg(&g_gph[(size_t)r0 * BB + lane]);
                acc1 += __ldcg(&g_gph[(size_t)(r0+1) * BB + lane]);
                gate_s[rl0 * 32 + lane] = acc0;
                gate_s[(rl0 + 1) * 32 + lane] = acc1;
            }
            __syncthreads();

            if (tid < 256) {
                int b = tid & 31, jo = tid >> 5;
                int j = jb * 8 + jo;
                float pre[4];
                #pragma unroll
                for (int g = 0; g < 4; g++) {
                    int r = g * 1024 + j;
                    pre[g] = gate_s[((g << 3) | jo) * 32 + b]
                           + E_s[(b << 5) | (g << 3) | jo]
                           + __ldg(&b_ih[r]) + __ldg(&b_hh[r]);
                }
                float ig = 1.f / (1.f + expf(-pre[0]));
                float fg = 1.f / (1.f + expf(-pre[1]));
                float gg = tanhf(pre[2]);
                float og = 1.f / (1.f + expf(-pre[3]));
                int idx = b * HH + j;
                float cn = fg * g_c[idx] + ig * gg;
                float hn = og * tanhf(cn);
                g_c[idx] = cn;
                g_h[idx] = hn;
                g_hs[((size_t)t * BB + b) * HH + j] = hn;
            }
        }
        gridbar(tgt); tgt += NB;
    }
}

// ---------------- small kernels ----------------
__global__ void k_zero() {
    int i = blockIdx.x * 1024 + threadIdx.x;
    g_h[i] = 0.f; g_c[i] = 0.f;
    if (i == 0) g_bar = 0u;
}

__global__ void k_copy_hc(float* __restrict__ out) {
    int i = blockIdx.x * 512 + threadIdx.x;
    const size_t OFF = (size_t)BB * TT * VV;
    out[OFF + i] = g_h[i];
    out[OFF + (size_t)BB*HH + i] = g_c[i];
}

// ---------------- launch ----------------
extern "C" void kernel_launch(void* const* d_in, const int* in_sizes, int n_in,
                              void* d_out, int out_size)
{
    const float* memory  = (const float*)d_in[0];
    const int*   captions= (const int*  )d_in[1];
    const float* emb     = (const float*)d_in[2];
    const float* attn_W  = (const float*)d_in[3];
    const float* W_ih    = (const float*)d_in[4];
    const float* W_hh    = (const float*)d_in[5];
    const float* b_ih    = (const float*)d_in[6];
    const float* b_hh    = (const float*)d_in[7];
    const float* W_out   = (const float*)d_in[8];
    const float* b_out   = (const float*)d_in[9];
    float* out = (float*)d_out;

    const int SMEM_RECUR = (32 * 1025 + 1024 + 1024) * 4;   // 139392 B

    static float *pM2 = nullptr, *pE = nullptr, *pHS = nullptr;
    if (!pM2) {
        cudaGetSymbolAddress((void**)&pM2, g_M2);
        cudaGetSymbolAddress((void**)&pE,  g_E);
        cudaGetSymbolAddress((void**)&pHS, g_hs);
        cudaFuncSetAttribute(k_recur, cudaFuncAttributeMaxDynamicSharedMemorySize, SMEM_RECUR);
    }

    k_zero<<<32, 1024>>>();

    // M2 = memory @ attn_W
    mma_gemm<<<dim3(HH/128, (BB*SS)/128), 256>>>(
        memory, attn_W, pM2, BB*SS, HH, HH, HH,
        nullptr, nullptr, nullptr, 2);

    // E = emb[captions] @ W_ih[:, :H]^T
    mma_gemm<<<dim3(RR/128, (BB*TT)/128), 256>>>(
        nullptr, W_ih, pE, BB*TT, RR, HH, 2048,
        captions, emb, nullptr, 0);

    // whole recurrence
    k_recur<<<NB, 1024, SMEM_RECUR>>>(memory, W_ih, W_hh, b_ih, b_hh);

    // logits = hs @ W_out^T + b_out
    mma_gemm<<<dim3(VV/128, (BB*TT)/128), 256>>>(
        pHS, W_out, out, BB*TT, VV, HH, HH,
        nullptr, nullptr, b_out, 1);

    k_copy_hc<<<64, 512>>>(out);
}

// round 7
// speedup vs baseline: 1.0171x; 1.0171x over previous
#include <cuda_runtime.h>
#include <cstdint>
#include <math.h>

#define BB 32
#define SS 196
#define TT 64
#define HH 1024
#define VV 32000
#define RR 4096   // 4*H
#define PADW 8
#define NB 148
#define SCW 2688  // total score warps

// ---------------- scratch ----------------
__device__ float g_M2[(size_t)BB*SS*HH];
__device__ float g_ET[(size_t)TT*RR*BB];      // E transposed [t][r][b]
__device__ float g_hs[(size_t)TT*BB*HH];      // rows = t*32+b
__device__ float g_Wph[(size_t)1024*512*8];   // W_hh packed  [j][kp][g0g1 pairs] (8 floats per (j,kp))
__device__ float g_Wpc[(size_t)1024*512*8];   // W_ih ctx-half packed
__device__ float g_h [BB*HH];
__device__ float g_c [BB*HH];
__device__ float g_ctx[BB*HH];
__device__ float g_scores[BB*SS];
__device__ unsigned g_bar;

// ---------------- helpers ----------------
__device__ __forceinline__ float f2tf32(float x) {
    uint32_t u; asm("cvt.rna.tf32.f32 %0, %1;" : "=r"(u) : "f"(x));
    return __uint_as_float(u);
}
__device__ __forceinline__ void mma_op(float* c, const uint32_t* a, const uint32_t* b) {
    asm volatile(
        "mma.sync.aligned.m16n8k8.row.col.f32.tf32.tf32.f32 "
        "{%0,%1,%2,%3},{%4,%5,%6,%7},{%8,%9},{%0,%1,%2,%3};"
        : "+f"(c[0]), "+f"(c[1]), "+f"(c[2]), "+f"(c[3])
        : "r"(a[0]), "r"(a[1]), "r"(a[2]), "r"(a[3]), "r"(b[0]), "r"(b[1]));
}
__device__ __forceinline__ void fma2op(unsigned long long& d,
                                       unsigned long long a, unsigned long long b) {
    asm("fma.rn.f32x2 %0, %1, %2, %0;" : "+l"(d) : "l"(a), "l"(b));
}
__device__ __forceinline__ float lohi(unsigned long long v) {
    return __uint_as_float((unsigned)v) + __uint_as_float((unsigned)(v >> 32));
}

// ---------------- tf32 tensor-core GEMM ----------------
// mode 0: C = A·Bt^T ; mode 1: logits (bias + row remap) ; mode 2: NN ;
// mode 3: E-transpose epilogue -> C[((m&63)*RR + n)*32 + (m>>6)]
__global__ __launch_bounds__(256, 2) void mma_gemm(
    const float* __restrict__ A, const float* __restrict__ Bsrc,
    float* __restrict__ C, int M, int N, int K, int ldb,
    const int* __restrict__ gatherIdx, const float* __restrict__ gatherTab,
    const float* __restrict__ bias, int mode)
{
    __shared__ float As[16][128 + PADW];
    __shared__ float Bs[16][128 + PADW];
    int tid = threadIdx.x;
    int n0 = blockIdx.x * 128, m0 = blockIdx.y * 128;
    int warp = tid >> 5, lane = tid & 31;
    int wm = warp >> 1, wn = warp & 1;
    int grp = lane >> 2, tg = lane & 3;

    float acc[2][8][4] = {};

    const float* arow[2];
    int ac4[2];
    #pragma unroll
    for (int it = 0; it < 2; it++) {
        int idx = tid + it * 256;
        int r = idx >> 2; ac4[it] = (idx & 3) * 4;
        arow[it] = gatherIdx ? (gatherTab + (size_t)gatherIdx[m0 + r] * K)
                             : (A + (size_t)(m0 + r) * K);
    }

    for (int k0 = 0; k0 < K; k0 += 16) {
        #pragma unroll
        for (int it = 0; it < 2; it++) {
            int idx = tid + it * 256;
            int r = idx >> 2;
            float4 v = *(const float4*)(arow[it] + k0 + ac4[it]);
            As[ac4[it]+0][r] = f2tf32(v.x); As[ac4[it]+1][r] = f2tf32(v.y);
            As[ac4[it]+2][r] = f2tf32(v.z); As[ac4[it]+3][r] = f2tf32(v.w);
        }
        if (mode == 2) {
            #pragma unroll
            for (int it = 0; it < 2; it++) {
                int idx = tid + it * 256;
                int r = idx >> 5, c4 = (idx & 31) * 4;
                float4 v = *(const float4*)(Bsrc + (size_t)(k0 + r) * ldb + n0 + c4);
                Bs[r][c4+0] = f2tf32(v.x); Bs[r][c4+1] = f2tf32(v.y);
                Bs[r][c4+2] = f2tf32(v.z); Bs[r][c4+3] = f2tf32(v.w);
            }
        } else {
            #pragma unroll
            for (int it = 0; it < 2; it++) {
                int idx = tid + it * 256;
                int r = idx >> 2, c4 = (idx & 3) * 4;
                float4 v = *(const float4*)(Bsrc + (size_t)(n0 + r) * ldb + k0 + c4);
                Bs[c4+0][r] = f2tf32(v.x); Bs[c4+1][r] = f2tf32(v.y);
                Bs[c4+2][r] = f2tf32(v.z); Bs[c4+3][r] = f2tf32(v.w);
            }
        }
        __syncthreads();

        #pragma unroll
        for (int ks = 0; ks < 2; ks++) {
            int kb = ks * 8;
            uint32_t af[2][4], bf[8][2];
            #pragma unroll
            for (int mt = 0; mt < 2; mt++) {
                int r = wm * 32 + mt * 16 + grp;
                af[mt][0] = __float_as_uint(As[kb+tg  ][r  ]);
                af[mt][1] = __float_as_uint(As[kb+tg  ][r+8]);
                af[mt][2] = __float_as_uint(As[kb+tg+4][r  ]);
                af[mt][3] = __float_as_uint(As[kb+tg+4][r+8]);
            }
            #pragma unroll
            for (int nt = 0; nt < 8; nt++) {
                int cix = wn * 64 + nt * 8 + grp;
                bf[nt][0] = __float_as_uint(Bs[kb+tg  ][cix]);
                bf[nt][1] = __float_as_uint(Bs[kb+tg+4][cix]);
            }
            #pragma unroll
            for (int mt = 0; mt < 2; mt++)
                #pragma unroll
                for (int nt = 0; nt < 8; nt++)
                    mma_op(acc[mt][nt], af[mt], bf[nt]);
        }
        __syncthreads();
    }

    #pragma unroll
    for (int mt = 0; mt < 2; mt++) {
        int mg = m0 + wm * 32 + mt * 16 + grp;
        #pragma unroll
        for (int nt = 0; nt < 8; nt++) {
            int ng = n0 + wn * 64 + nt * 8 + tg * 2;
            float* a4 = acc[mt][nt];
            if (mode == 1) {
                float b0 = __ldg(bias + ng), b1 = __ldg(bias + ng + 1);
                size_t r1 = ((size_t)(mg & 31) * TT + (mg >> 5)) * N;
                size_t r2 = ((size_t)((mg+8) & 31) * TT + ((mg+8) >> 5)) * N;
                *(float2*)(C + r1 + ng) = make_float2(a4[0] + b0, a4[1] + b1);
                *(float2*)(C + r2 + ng) = make_float2(a4[2] + b0, a4[3] + b1);
            } else if (mode == 3) {
                int b1i = mg >> 6,     t1 = mg & 63;
                int b2i = (mg+8) >> 6, t2 = (mg+8) & 63;
                size_t p1 = ((size_t)t1 * RR + ng) * 32 + b1i;
                size_t p2 = ((size_t)t2 * RR + ng) * 32 + b2i;
                C[p1] = a4[0]; C[p1 + 32] = a4[1];
                C[p2] = a4[2]; C[p2 + 32] = a4[3];
            } else {
                *(float2*)(C + (size_t)mg * N + ng)       = make_float2(a4[0], a4[1]);
                *(float2*)(C + (size_t)(mg + 8) * N + ng) = make_float2(a4[2], a4[3]);
            }
        }
    }
}

// ---------------- weight packing: per (j,kp): 8 floats = 4 gates x 2 k ----------------
__global__ __launch_bounds__(256) void k_packW(
    const float* __restrict__ W_ih, const float* __restrict__ W_hh)
{
    int idx = blockIdx.x * 256 + threadIdx.x;    // 0..524287
    int j = idx >> 9, kp = idx & 511;
    {
        float2 v0 = *(const float2*)&W_hh[((size_t)(0*1024 + j))*HH + 2*kp];
        float2 v1 = *(const float2*)&W_hh[((size_t)(1*1024 + j))*HH + 2*kp];
        float2 v2 = *(const float2*)&W_hh[((size_t)(2*1024 + j))*HH + 2*kp];
        float2 v3 = *(const float2*)&W_hh[((size_t)(3*1024 + j))*HH + 2*kp];
        ((float4*)g_Wph)[(size_t)idx*2]   = make_float4(v0.x, v0.y, v1.x, v1.y);
        ((float4*)g_Wph)[(size_t)idx*2+1] = make_float4(v2.x, v2.y, v3.x, v3.y);
    }
    {
        float2 v0 = *(const float2*)&W_ih[((size_t)(0*1024 + j))*2048 + 1024 + 2*kp];
        float2 v1 = *(const float2*)&W_ih[((size_t)(1*1024 + j))*2048 + 1024 + 2*kp];
        float2 v2 = *(const float2*)&W_ih[((size_t)(2*1024 + j))*2048 + 1024 + 2*kp];
        float2 v3 = *(const float2*)&W_ih[((size_t)(3*1024 + j))*2048 + 1024 + 2*kp];
        ((float4*)g_Wpc)[(size_t)idx*2]   = make_float4(v0.x, v0.y, v1.x, v1.y);
        ((float4*)g_Wpc)[(size_t)idx*2+1] = make_float4(v2.x, v2.y, v3.x, v3.y);
    }
}

// ---------------- no-CCTL global barrier ----------------
__device__ __forceinline__ void gridbar(unsigned target) {
    __syncthreads();
    if (threadIdx.x == 0) {
        unsigned one = 1u, x;
        asm volatile("red.release.gpu.global.add.u32 [%0], %1;"
                     :: "l"(&g_bar), "r"(one) : "memory");
        do {
            asm volatile("ld.acquire.gpu.global.u32 %0, [%1];"
                         : "=r"(x) : "l"(&g_bar));
        } while (x < target);
    }
    __syncthreads();
}

// ---------------- gate half-GEMM: 4 gates of one j, one K-half, f32x2 ----------------
__device__ __forceinline__ void gate_half(
    const float* __restrict__ Wp, const float* xsm,
    float* outp, int j, int hf, int lane)
{
    const float4* wp = (const float4*)Wp + ((size_t)j * 512 + hf * 256) * 2;
    const float2* xp = (const float2*)(xsm + lane * 1026) + hf * 256;
    unsigned long long a0 = 0, a1 = 0, a2 = 0, a3 = 0;
    #pragma unroll 4
    for (int kp = 0; kp < 256; kp++) {
        float4 wA = wp[2*kp], wB = wp[2*kp + 1];
        float2 xv = xp[kp];
        unsigned long long x2 = *(unsigned long long*)&xv;
        fma2op(a0, *(unsigned long long*)&wA.x, x2);
        fma2op(a1, *(unsigned long long*)&wA.z, x2);
        fma2op(a2, *(unsigned long long*)&wB.x, x2);
        fma2op(a3, *(unsigned long long*)&wB.z, x2);
    }
    outp[0]  = lohi(a0);
    outp[32] = lohi(a1);
    outp[64] = lohi(a2);
    outp[96] = lohi(a3);
}

// ---------------- persistent recurrence ----------------
// smem: xsm[32][1026] | gph[2][8][4][32] | gpc[2][8][4][32] | p2s[1536]
__global__ __launch_bounds__(1024, 1) void k_recur(
    const float* __restrict__ memory,
    const float* __restrict__ b_ih, const float* __restrict__ b_hh)
{
    extern __shared__ float smem[];
    float* xsm = smem;                  // 32*1026 = 32832
    float* gph = smem + 32 * 1026;      // 2048
    float* gpc = gph + 2048;            // 2048
    float* p2s = gpc + 2048;            // 1536

    const int tid = threadIdx.x;
    const int bid = blockIdx.x;
    const int w = tid >> 5, lane = tid & 31;
    const bool gateblk = (bid < 128);
    unsigned tgt = NB;

    for (int t = 0; t < TT; t++) {
        // ======== P1: stage h ; hh-gates ; scores ========
        if (gateblk) {
            for (int i = tid; i < BB * HH; i += 1024)
                xsm[(i >> 10) * 1026 + (i & 1023)] = __ldcg(&g_h[i]);
        }
        __syncthreads();

        if (gateblk && w < 16) {
            int jl = w & 7, hf = w >> 3;
            gate_half(g_Wph, xsm, gph + ((hf*8 + jl)*4)*32 + lane,
                      bid*8 + jl, hf, lane);
        }
        {
            int swid = gateblk ? (w >= 16 ? bid*16 + (w - 16) : -1)
                               : (2048 + (bid - 128)*32 + w);
            if (swid >= 0) {
                for (int p = swid; p < BB * SS; p += SCW) {
                    int b = p / SS;
                    const float4* m4 = (const float4*)(g_M2 + (size_t)p * HH);
                    const float4* h4 = (const float4*)(g_h + b * HH);
                    float a = 0.f;
                    #pragma unroll
                    for (int i = 0; i < 8; i++) {
                        float4 mv = m4[i*32 + lane];
                        float4 hv = __ldcg(&h4[i*32 + lane]);
                        a += mv.x*hv.x + mv.y*hv.y + mv.z*hv.z + mv.w*hv.w;
                    }
                    #pragma unroll
                    for (int o = 16; o; o >>= 1) a += __shfl_xor_sync(0xffffffffu, a, o);
                    if (!lane) g_scores[p] = a;
                }
            }
        }
        gridbar(tgt); tgt += NB;

        // ======== P2: softmax + ctx (blocks 0..127) ========
        if (gateblk) {
            float* red  = p2s;
            float* swp  = p2s + 256;
            float* part = p2s + 512;
            int b = bid >> 2, jblk = bid & 3;
            float v = -1e30f;
            if (tid < 256) {
                v = (tid < SS) ? __ldcg(&g_scores[b * SS + tid]) : -1e30f;
                red[tid] = v;
            }
            __syncthreads();
            for (int o = 128; o; o >>= 1) { if (tid < o) red[tid] = fmaxf(red[tid], red[tid+o]); __syncthreads(); }
            float mx = red[0]; __syncthreads();
            float e = 0.f;
            if (tid < 256) { e = (tid < SS) ? expf(v - mx) : 0.f; red[tid] = e; }
            __syncthreads();
            for (int o = 128; o; o >>= 1) { if (tid < o) red[tid] += red[tid+o]; __syncthreads(); }
            float inv = 1.f / red[0];
            if (tid < 256) swp[tid] = e * inv;
            __syncthreads();

            int jj = tid & 255, sp = tid >> 8;
            int j = jblk * 256 + jj;
            const float* mp = memory + ((size_t)b * SS + sp * 49) * HH + j;
            float acc = 0.f;
            #pragma unroll 7
            for (int s = 0; s < 49; s++)
                acc += swp[sp * 49 + s] * mp[(size_t)s * HH];
            part[sp * 256 + jj] = acc;
            __syncthreads();
            if (tid < 256)
                g_ctx[b * HH + j] = part[jj] + part[256+jj] + part[512+jj] + part[768+jj];
        }
        gridbar(tgt); tgt += NB;

        // ======== P3: stage ctx ; ctx-gates ; cell ========
        if (gateblk) {
            for (int i = tid; i < BB * HH; i += 1024)
                xsm[(i >> 10) * 1026 + (i & 1023)] = __ldcg(&g_ctx[i]);
        }
        __syncthreads();
        if (gateblk && w < 16) {
            int jl = w & 7, hf = w >> 3;
            gate_half(g_Wpc, xsm, gpc + ((hf*8 + jl)*4)*32 + lane,
                      bid*8 + jl, hf, lane);
        }
        __syncthreads();
        if (gateblk && w < 8) {
            int j = bid * 8 + w;
            float pre[4];
            #pragma unroll
            for (int g = 0; g < 4; g++) {
                int o = (w*4 + g)*32 + lane;
                pre[g] = gph[o] + gph[1024 + o] + gpc[o] + gpc[1024 + o]
                       + __ldg(&g_ET[((size_t)t * RR + g*1024 + j) * 32 + lane])
                       + __ldg(&b_ih[g*1024 + j]) + __ldg(&b_hh[g*1024 + j]);
            }
            float ig = 1.f / (1.f + expf(-pre[0]));
            float fg = 1.f / (1.f + expf(-pre[1]));
            float gg = tanhf(pre[2]);
            float og = 1.f / (1.f + expf(-pre[3]));
            int idx = lane * HH + j;
            float cn = fg * g_c[idx] + ig * gg;
            float hn = og * tanhf(cn);
            g_c[idx] = cn;
            g_h[idx] = hn;
            g_hs[((size_t)t * BB + lane) * HH + j] = hn;
        }
        gridbar(tgt); tgt += NB;
    }
}

// ---------------- small kernels ----------------
__global__ void k_zero() {
    int i = blockIdx.x * 1024 + threadIdx.x;
    g_h[i] = 0.f; g_c[i] = 0.f;
    if (i == 0) g_bar = 0u;
}

__global__ void k_copy_hc(float* __restrict__ out) {
    int i = blockIdx.x * 512 + threadIdx.x;
    const size_t OFF = (size_t)BB * TT * VV;
    out[OFF + i] = g_h[i];
    out[OFF + (size_t)BB*HH + i] = g_c[i];
}

// ---------------- launch ----------------
extern "C" void kernel_launch(void* const* d_in, const int* in_sizes, int n_in,
                              void* d_out, int out_size)
{
    const float* memory  = (const float*)d_in[0];
    const int*   captions= (const int*  )d_in[1];
    const float* emb     = (const float*)d_in[2];
    const float* attn_W  = (const float*)d_in[3];
    const float* W_ih    = (const float*)d_in[4];
    const float* W_hh    = (const float*)d_in[5];
    const float* b_ih    = (const float*)d_in[6];
    const float* b_hh    = (const float*)d_in[7];
    const float* W_out   = (const float*)d_in[8];
    const float* b_out   = (const float*)d_in[9];
    float* out = (float*)d_out;

    const int SMEM_RECUR = (32*1026 + 2048 + 2048 + 1536) * 4;   // 153856 B

    static float *pM2 = nullptr, *pET = nullptr, *pHS = nullptr;
    if (!pM2) {
        cudaGetSymbolAddress((void**)&pM2, g_M2);
        cudaGetSymbolAddress((void**)&pET, g_ET);
        cudaGetSymbolAddress((void**)&pHS, g_hs);
        cudaFuncSetAttribute(k_recur, cudaFuncAttributeMaxDynamicSharedMemorySize, SMEM_RECUR);
    }

    k_zero<<<32, 1024>>>();

    // M2 = memory @ attn_W
    mma_gemm<<<dim3(HH/128, (BB*SS)/128), 256>>>(
        memory, attn_W, pM2, BB*SS, HH, HH, HH,
        nullptr, nullptr, nullptr, 2);

    // E^T = (emb[captions] @ W_ih[:, :H]^T) transposed to [t][r][b]
    mma_gemm<<<dim3(RR/128, (BB*TT)/128), 256>>>(
        nullptr, W_ih, pET, BB*TT, RR, HH, 2048,
        captions, emb, nullptr, 3);

    // packed weights
    k_packW<<<2048, 256>>>(W_ih, W_hh);

    // whole recurrence
    k_recur<<<NB, 1024, SMEM_RECUR>>>(memory, b_ih, b_hh);

    // logits = hs @ W_out^T + b_out
    mma_gemm<<<dim3(VV/128, (BB*TT)/128), 256>>>(
        pHS, W_out, out, BB*TT, VV, HH, HH,
        nullptr, nullptr, b_out, 1);

    k_copy_hc<<<64, 512>>>(out);
}

// round 8
// speedup vs baseline: 2.1023x; 2.0669x over previous
#include <cuda_runtime.h>
#include <cstdint>
#include <math.h>

#define BB 32
#define SS 196
#define TT 64
#define HH 1024
#define VV 32000
#define RR 4096
#define PADW 8
#define NB 148

// k_recur smem byte offsets
#define OFF_W    128
#define OFF_X    (128 + 32768)
#define OFF_GATE (128 + 65536)          // 65664
#define OFF_P2S  (OFF_GATE + 4096)      // 69760
#define SMEM_RECUR (OFF_P2S + 6144)     // 75904

// ---------------- scratch ----------------
__device__ float g_M2[(size_t)BB*SS*HH];
__device__ float g_ET[(size_t)TT*RR*BB];       // E transposed [t][r][b]
__device__ float g_hs[(size_t)TT*BB*HH];       // rows = t*32+b
__device__ float g_Wf[(size_t)128*16*4096];    // fragment-packed gate weights
__device__ float g_xf[(size_t)24*4096];        // x fragments: ctx chunks 0-7, h chunks 8-23 (2x parity)
__device__ float g_h [BB*HH];
__device__ float g_c [BB*HH];
__device__ float g_scores[BB*SS];
__device__ unsigned g_bar;

// ---------------- helpers ----------------
__device__ __forceinline__ float f2tf32(float x) {
    uint32_t u; asm("cvt.rna.tf32.f32 %0, %1;" : "=r"(u) : "f"(x));
    return __uint_as_float(u);
}
__device__ __forceinline__ void mma_op(float* c, const uint32_t* a, const uint32_t* b) {
    asm volatile(
        "mma.sync.aligned.m16n8k8.row.col.f32.tf32.tf32.f32 "
        "{%0,%1,%2,%3},{%4,%5,%6,%7},{%8,%9},{%0,%1,%2,%3};"
        : "+f"(c[0]), "+f"(c[1]), "+f"(c[2]), "+f"(c[3])
        : "r"(a[0]), "r"(a[1]), "r"(a[2]), "r"(a[3]), "r"(b[0]), "r"(b[1]));
}
__device__ __forceinline__ uint32_t smem_u32(const void* p) {
    uint32_t a;
    asm("{ .reg .u64 t; cvta.to.shared.u64 t, %1; cvt.u32.u64 %0, t; }" : "=r"(a) : "l"(p));
    return a;
}
// x-fragment offset for value x(k, n); h half (k>=1024) parity-double-buffered
__device__ __forceinline__ size_t xf_off(int k, int n, int parity) {
    int cc = k >> 7;
    int ccp = (cc < 8) ? cc : (cc + parity * 8);
    int c8 = (k >> 3) & 15;
    int nt = n >> 3;
    int ln = ((n & 7) << 2) | (k & 3);
    int q  = (k >> 2) & 1;
    return ((size_t)(ccp * 16 + c8) * 4 + nt) * 64 + (size_t)ln * 2 + q;
}

#define MB_WAIT(mbar, par) do { uint32_t _d; \
    do { asm volatile("{\n\t.reg .pred p;\n\t" \
        "mbarrier.try_wait.parity.acquire.cta.shared::cta.b64 p, [%1], %2;\n\t" \
        "selp.b32 %0, 1, 0, p;\n\t}" \
        : "=r"(_d) : "r"(mbar), "r"((uint32_t)(par)) : "memory"); } while (!_d); } while (0)

// ---------------- tf32 tensor-core GEMM (unchanged; modes 1/2/3 used) ----------------
__global__ __launch_bounds__(256, 2) void mma_gemm(
    const float* __restrict__ A, const float* __restrict__ Bsrc,
    float* __restrict__ C, int M, int N, int K, int ldb,
    const int* __restrict__ gatherIdx, const float* __restrict__ gatherTab,
    const float* __restrict__ bias, int mode)
{
    __shared__ float As[16][128 + PADW];
    __shared__ float Bs[16][128 + PADW];
    int tid = threadIdx.x;
    int n0 = blockIdx.x * 128, m0 = blockIdx.y * 128;
    int warp = tid >> 5, lane = tid & 31;
    int wm = warp >> 1, wn = warp & 1;
    int grp = lane >> 2, tg = lane & 3;

    float acc[2][8][4] = {};

    const float* arow[2];
    int ac4[2];
    #pragma unroll
    for (int it = 0; it < 2; it++) {
        int idx = tid + it * 256;
        int r = idx >> 2; ac4[it] = (idx & 3) * 4;
        arow[it] = gatherIdx ? (gatherTab + (size_t)gatherIdx[m0 + r] * K)
                             : (A + (size_t)(m0 + r) * K);
    }

    for (int k0 = 0; k0 < K; k0 += 16) {
        #pragma unroll
        for (int it = 0; it < 2; it++) {
            int idx = tid + it * 256;
            int r = idx >> 2;
            float4 v = *(const float4*)(arow[it] + k0 + ac4[it]);
            As[ac4[it]+0][r] = f2tf32(v.x); As[ac4[it]+1][r] = f2tf32(v.y);
            As[ac4[it]+2][r] = f2tf32(v.z); As[ac4[it]+3][r] = f2tf32(v.w);
        }
        if (mode == 2) {
            #pragma unroll
            for (int it = 0; it < 2; it++) {
                int idx = tid + it * 256;
                int r = idx >> 5, c4 = (idx & 31) * 4;
                float4 v = *(const float4*)(Bsrc + (size_t)(k0 + r) * ldb + n0 + c4);
                Bs[r][c4+0] = f2tf32(v.x); Bs[r][c4+1] = f2tf32(v.y);
                Bs[r][c4+2] = f2tf32(v.z); Bs[r][c4+3] = f2tf32(v.w);
            }
        } else {
            #pragma unroll
            for (int it = 0; it < 2; it++) {
                int idx = tid + it * 256;
                int r = idx >> 2, c4 = (idx & 3) * 4;
                float4 v = *(const float4*)(Bsrc + (size_t)(n0 + r) * ldb + k0 + c4);
                Bs[c4+0][r] = f2tf32(v.x); Bs[c4+1][r] = f2tf32(v.y);
                Bs[c4+2][r] = f2tf32(v.z); Bs[c4+3][r] = f2tf32(v.w);
            }
        }
        __syncthreads();

        #pragma unroll
        for (int ks = 0; ks < 2; ks++) {
            int kb = ks * 8;
            uint32_t af[2][4], bf[8][2];
            #pragma unroll
            for (int mt = 0; mt < 2; mt++) {
                int r = wm * 32 + mt * 16 + grp;
                af[mt][0] = __float_as_uint(As[kb+tg  ][r  ]);
                af[mt][1] = __float_as_uint(As[kb+tg  ][r+8]);
                af[mt][2] = __float_as_uint(As[kb+tg+4][r  ]);
                af[mt][3] = __float_as_uint(As[kb+tg+4][r+8]);
            }
            #pragma unroll
            for (int nt = 0; nt < 8; nt++) {
                int cix = wn * 64 + nt * 8 + grp;
                bf[nt][0] = __float_as_uint(Bs[kb+tg  ][cix]);
                bf[nt][1] = __float_as_uint(Bs[kb+tg+4][cix]);
            }
            #pragma unroll
            for (int mt = 0; mt < 2; mt++)
                #pragma unroll
                for (int nt = 0; nt < 8; nt++)
                    mma_op(acc[mt][nt], af[mt], bf[nt]);
        }
        __syncthreads();
    }

    #pragma unroll
    for (int mt = 0; mt < 2; mt++) {
        int mg = m0 + wm * 32 + mt * 16 + grp;
        #pragma unroll
        for (int nt = 0; nt < 8; nt++) {
            int ng = n0 + wn * 64 + nt * 8 + tg * 2;
            float* a4 = acc[mt][nt];
            if (mode == 1) {
                float b0 = __ldg(bias + ng), b1 = __ldg(bias + ng + 1);
                size_t r1 = ((size_t)(mg & 31) * TT + (mg >> 5)) * N;
                size_t r2 = ((size_t)((mg+8) & 31) * TT + ((mg+8) >> 5)) * N;
                *(float2*)(C + r1 + ng) = make_float2(a4[0] + b0, a4[1] + b1);
                *(float2*)(C + r2 + ng) = make_float2(a4[2] + b0, a4[3] + b1);
            } else if (mode == 3) {
                int b1i = mg >> 6,     t1 = mg & 63;
                int b2i = (mg+8) >> 6, t2 = (mg+8) & 63;
                size_t p1 = ((size_t)t1 * RR + ng) * 32 + b1i;
                size_t p2 = ((size_t)t2 * RR + ng) * 32 + b2i;
                C[p1] = a4[0]; C[p1 + 32] = a4[1];
                C[p2] = a4[2]; C[p2 + 32] = a4[3];
            } else {
                *(float2*)(C + (size_t)mg * N + ng)       = make_float2(a4[0], a4[1]);
                *(float2*)(C + (size_t)(mg + 8) * N + ng) = make_float2(a4[2], a4[3]);
            }
        }
    }
}

// ---------------- weight fragment pack ----------------
// out float4 index: (((blk*16 + cc)*16 + c8)*2 + mt)*32 + lane
// value q: m = mt*16 + (lane>>2) + 8*(q&1) -> g=m>>3, jo=m&7, r=g*1024+blk*8+jo
//          k = (cc*16+c8)*8 + (lane&3) + 4*(q>>1)
__global__ __launch_bounds__(256) void k_packWF(
    const float* __restrict__ W_ih, const float* __restrict__ W_hh)
{
    int idx = blockIdx.x * 256 + threadIdx.x;    // 0..2097151
    int lane = idx & 31;
    int mt   = (idx >> 5) & 1;
    int c8   = (idx >> 6) & 15;
    int cc   = (idx >> 10) & 15;
    int blk  = idx >> 14;
    float4 v;
    float* o = (float*)&v;
    #pragma unroll
    for (int q = 0; q < 4; q++) {
        int m = mt * 16 + (lane >> 2) + 8 * (q & 1);
        int g = m >> 3, jo = m & 7;
        int r = g * 1024 + blk * 8 + jo;
        int k = (cc * 16 + c8) * 8 + (lane & 3) + 4 * (q >> 1);
        float wv = (k < 1024) ? W_ih[(size_t)r * 2048 + 1024 + k]
                              : W_hh[(size_t)r * 1024 + (k - 1024)];
        o[q] = f2tf32(wv);
    }
    ((float4*)g_Wf)[idx] = v;
}

// ---------------- no-CCTL global barrier ----------------
__device__ __forceinline__ void gridbar(unsigned target) {
    __syncthreads();
    if (threadIdx.x == 0) {
        unsigned one = 1u, x;
        asm volatile("red.release.gpu.global.add.u32 [%0], %1;"
                     :: "l"(&g_bar), "r"(one) : "memory");
        do {
            asm volatile("ld.acquire.gpu.global.u32 %0, [%1];"
                         : "=r"(x) : "l"(&g_bar));
        } while (x < target);
    }
    __syncthreads();
}

// ---------------- persistent recurrence ----------------
__global__ __launch_bounds__(1024, 1) void k_recur(
    const float* __restrict__ memory,
    const float* __restrict__ b_ih, const float* __restrict__ b_hh)
{
    extern __shared__ char smem[];
    float* gate_s = (float*)(smem + OFF_GATE);
    float* p2s    = (float*)(smem + OFF_P2S);
    const uint32_t sbase = smem_u32(smem);
    const uint32_t mb0 = sbase, mb1 = sbase + 8;

    const int tid = threadIdx.x, bid = blockIdx.x;
    const int w = tid >> 5, lane = tid & 31;
    const bool gateblk = (bid < 128);

    if (tid == 0) {
        asm volatile("mbarrier.init.shared.b64 [%0], %1;" :: "r"(mb0), "r"(1u) : "memory");
        asm volatile("mbarrier.init.shared.b64 [%0], %1;" :: "r"(mb1), "r"(1u) : "memory");
    }
    __syncthreads();

    unsigned tgt = NB;

    for (int t = 0; t < TT; t++) {
        // ======== P1: scores[b,s] = h[b] . M2[b,s,:]  (all 148 blocks) ========
        for (int p = bid * 32 + w; p < BB * SS; p += NB * 32) {
            int b = p / SS;
            const float4* m4 = (const float4*)(g_M2 + (size_t)p * HH);
            const float4* h4 = (const float4*)(g_h + b * HH);
            float a = 0.f;
            #pragma unroll
            for (int i = 0; i < 8; i++) {
                float4 mv = m4[i * 32 + lane];
                float4 hv = __ldcg(&h4[i * 32 + lane]);
                a += mv.x*hv.x + mv.y*hv.y + mv.z*hv.z + mv.w*hv.w;
            }
            #pragma unroll
            for (int o = 16; o; o >>= 1) a += __shfl_xor_sync(0xffffffffu, a, o);
            if (!lane) g_scores[p] = a;
        }
        gridbar(tgt); tgt += NB;

        // ======== P2: softmax + ctx -> x fragments (blocks 0..127) ========
        if (gateblk) {
            float* red  = p2s;          // 256
            float* swp  = p2s + 256;    // 256
            float* part = p2s + 512;    // 1024
            int b = bid >> 2, jblk = bid & 3;
            float v = -1e30f;
            if (tid < 256) {
                v = (tid < SS) ? __ldcg(&g_scores[b * SS + tid]) : -1e30f;
                red[tid] = v;
            }
            __syncthreads();
            for (int o = 128; o; o >>= 1) { if (tid < o) red[tid] = fmaxf(red[tid], red[tid+o]); __syncthreads(); }
            float mx = red[0]; __syncthreads();
            float e = 0.f;
            if (tid < 256) { e = (tid < SS) ? expf(v - mx) : 0.f; red[tid] = e; }
            __syncthreads();
            for (int o = 128; o; o >>= 1) { if (tid < o) red[tid] += red[tid+o]; __syncthreads(); }
            float inv = 1.f / red[0];
            if (tid < 256) swp[tid] = e * inv;
            __syncthreads();

            int jj = tid & 255, sp = tid >> 8;
            int j = jblk * 256 + jj;
            const float* mp = memory + ((size_t)b * SS + sp * 49) * HH + j;
            float acc = 0.f;
            #pragma unroll 7
            for (int s = 0; s < 49; s++)
                acc += swp[sp * 49 + s] * mp[(size_t)s * HH];
            part[sp * 256 + jj] = acc;
            __syncthreads();
            if (tid < 256) {
                float cv = part[jj] + part[256+jj] + part[512+jj] + part[768+jj];
                g_xf[xf_off(j, b, 0)] = f2tf32(cv);
            }
        }
        gridbar(tgt); tgt += NB;

        // ======== P3: gates (bulk-copy + tf32 mma pipeline) + cell ========
        if (gateblk) {
            if (tid < 256) {
                const int w8 = tid >> 5;
                const int mt = w8 & 1, nt = w8 >> 1;
                const int grp = lane >> 2, tg = lane & 3;
                const int par = t & 1;
                float acc[4] = {0.f, 0.f, 0.f, 0.f};

                auto issue = [&](int cc) {
                    uint32_t mb = (cc & 1) ? mb1 : mb0;
                    uint32_t wd = sbase + OFF_W + (cc & 1) * 16384;
                    uint32_t xd = sbase + OFF_X + (cc & 1) * 16384;
                    const float* ws = g_Wf + ((size_t)bid * 16 + cc) * 4096;
                    int ccp = (cc < 8) ? cc : (cc + par * 8);
                    const float* xs = g_xf + (size_t)ccp * 4096;
                    asm volatile("mbarrier.arrive.expect_tx.shared.b64 _, [%0], %1;"
                                 :: "r"(mb), "r"(32768u) : "memory");
                    asm volatile("cp.async.bulk.shared::cta.global.mbarrier::complete_tx::bytes "
                                 "[%0], [%1], %2, [%3];"
                                 :: "r"(wd), "l"(ws), "r"(16384u), "r"(mb) : "memory");
                    asm volatile("cp.async.bulk.shared::cta.global.mbarrier::complete_tx::bytes "
                                 "[%0], [%1], %2, [%3];"
                                 :: "r"(xd), "l"(xs), "r"(16384u), "r"(mb) : "memory");
                };

                if (tid == 0) { issue(0); issue(1); }

                #pragma unroll
                for (int i = 0; i < 16; i++) {
                    uint32_t mb = (i & 1) ? mb1 : mb0;
                    MB_WAIT(mb, (i >> 1) & 1);
                    const float4* wb = (const float4*)(smem + OFF_W + (i & 1) * 16384);
                    const float2* xb = (const float2*)(smem + OFF_X + (i & 1) * 16384);
                    #pragma unroll
                    for (int c8 = 0; c8 < 16; c8++) {
                        float4 a4 = wb[(c8 * 2 + mt) * 32 + lane];
                        float2 b2 = xb[(c8 * 4 + nt) * 32 + lane];
                        mma_op(acc, (const uint32_t*)&a4, (const uint32_t*)&b2);
                    }
                    asm volatile("bar.sync 7, 256;" ::: "memory");
                    if (tid == 0 && i < 14) issue(i + 2);
                }

                *(float2*)&gate_s[(mt*16 + grp    ) * 32 + nt*8 + tg*2] = make_float2(acc[0], acc[1]);
                *(float2*)&gate_s[(mt*16 + grp + 8) * 32 + nt*8 + tg*2] = make_float2(acc[2], acc[3]);
            }
            __syncthreads();
            if (tid < 256) {
                int b = tid & 31, jo = tid >> 5;
                int j = bid * 8 + jo;
                float pre[4];
                #pragma unroll
                for (int g = 0; g < 4; g++) {
                    pre[g] = gate_s[(g*8 + jo) * 32 + b]
                           + __ldg(&g_ET[((size_t)t * RR + g*1024 + j) * 32 + b])
                           + __ldg(&b_ih[g*1024 + j]) + __ldg(&b_hh[g*1024 + j]);
                }
                float ig = 1.f / (1.f + expf(-pre[0]));
                float fg = 1.f / (1.f + expf(-pre[1]));
                float gg = tanhf(pre[2]);
                float og = 1.f / (1.f + expf(-pre[3]));
                int idx = b * HH + j;
                float cn = fg * g_c[idx] + ig * gg;
                float hn = og * tanhf(cn);
                g_c[idx] = cn;
                g_h[idx] = hn;
                g_hs[((size_t)t * BB + b) * HH + j] = hn;
                g_xf[xf_off(1024 + j, b, (t + 1) & 1)] = f2tf32(hn);
            }
        }
        gridbar(tgt); tgt += NB;
    }
}

// ---------------- small kernels ----------------
__global__ void k_zero() {
    int i = blockIdx.x * 1024 + threadIdx.x;   // 32768 threads
    g_h[i] = 0.f; g_c[i] = 0.f;
    g_xf[i] = 0.f; g_xf[i + 32768] = 0.f; g_xf[i + 65536] = 0.f;
    if (i == 0) g_bar = 0u;
}

__global__ void k_copy_hc(float* __restrict__ out) {
    int i = blockIdx.x * 512 + threadIdx.x;
    const size_t OFF = (size_t)BB * TT * VV;
    out[OFF + i] = g_h[i];
    out[OFF + (size_t)BB*HH + i] = g_c[i];
}

// ---------------- launch ----------------
extern "C" void kernel_launch(void* const* d_in, const int* in_sizes, int n_in,
                              void* d_out, int out_size)
{
    const float* memory  = (const float*)d_in[0];
    const int*   captions= (const int*  )d_in[1];
    const float* emb     = (const float*)d_in[2];
    const float* attn_W  = (const float*)d_in[3];
    const float* W_ih    = (const float*)d_in[4];
    const float* W_hh    = (const float*)d_in[5];
    const float* b_ih    = (const float*)d_in[6];
    const float* b_hh    = (const float*)d_in[7];
    const float* W_out   = (const float*)d_in[8];
    const float* b_out   = (const float*)d_in[9];
    float* out = (float*)d_out;

    static float *pM2 = nullptr, *pET = nullptr, *pHS = nullptr;
    if (!pM2) {
        cudaGetSymbolAddress((void**)&pM2, g_M2);
        cudaGetSymbolAddress((void**)&pET, g_ET);
        cudaGetSymbolAddress((void**)&pHS, g_hs);
        cudaFuncSetAttribute(k_recur, cudaFuncAttributeMaxDynamicSharedMemorySize, SMEM_RECUR);
    }

    k_zero<<<32, 1024>>>();

    // M2 = memory @ attn_W
    mma_gemm<<<dim3(HH/128, (BB*SS)/128), 256>>>(
        memory, attn_W, pM2, BB*SS, HH, HH, HH,
        nullptr, nullptr, nullptr, 2);

    // E^T = (emb[captions] @ W_ih[:, :H]^T) transposed to [t][r][b]
    mma_gemm<<<dim3(RR/128, (BB*TT)/128), 256>>>(
        nullptr, W_ih, pET, BB*TT, RR, HH, 2048,
        captions, emb, nullptr, 3);

    // fragment-packed gate weights
    k_packWF<<<8192, 256>>>(W_ih, W_hh);

    // whole recurrence
    k_recur<<<NB, 1024, SMEM_RECUR>>>(memory, b_ih, b_hh);

    // logits = hs @ W_out^T + b_out
    mma_gemm<<<dim3(VV/128, (BB*TT)/128), 256>>>(
        pHS, W_out, out, BB*TT, VV, HH, HH,
        nullptr, nullptr, b_out, 1);

    k_copy_hc<<<64, 512>>>(out);
}

// round 9
// speedup vs baseline: 2.8801x; 1.3700x over previous
#include <cuda_runtime.h>
#include <cstdint>
#include <math.h>

#define BB 32
#define SS 196
#define TT 64
#define HH 1024
#define VV 32000
#define RR 4096
#define PADW 8
#define NB 148

// k_recur smem byte offsets
#define OFF_W    128
#define OFF_X    (128 + 32768)
#define OFF_GATE (128 + 65536)
#define OFF_P2S  (OFF_GATE + 4096)
#define SMEM_RECUR (OFF_P2S + 6144)

// k_logits smem: 3 stages x (16KB A + 16KB B), mbarriers at base
#define SMEM_LOG (128 + 3*32768)

// ---------------- scratch ----------------
__device__ float g_M2[(size_t)BB*SS*HH];
__device__ float g_ET[(size_t)TT*RR*BB];       // E transposed [t][r][b]
__device__ float g_Wf[(size_t)128*16*4096];    // fragment-packed gate weights
__device__ float g_xf[(size_t)24*4096];        // x fragments (ctx 0-7, h 8-23 dbl-buffered)
__device__ float g_Af[(size_t)16*131072];      // logits A fragments [mblk][c8][mt][lane][4]
__device__ float g_Wo[(size_t)32000*1024];     // logits B fragments [nblk][c8][nt][lane][2]
__device__ float g_h [BB*HH];
__device__ float g_c [BB*HH];
__device__ float g_scores[BB*SS];
__device__ unsigned g_bar;

// ---------------- helpers ----------------
__device__ __forceinline__ float f2tf32(float x) {
    uint32_t u; asm("cvt.rna.tf32.f32 %0, %1;" : "=r"(u) : "f"(x));
    return __uint_as_float(u);
}
__device__ __forceinline__ void mma_op(float* c, const uint32_t* a, const uint32_t* b) {
    asm volatile(
        "mma.sync.aligned.m16n8k8.row.col.f32.tf32.tf32.f32 "
        "{%0,%1,%2,%3},{%4,%5,%6,%7},{%8,%9},{%0,%1,%2,%3};"
        : "+f"(c[0]), "+f"(c[1]), "+f"(c[2]), "+f"(c[3])
        : "r"(a[0]), "r"(a[1]), "r"(a[2]), "r"(a[3]), "r"(b[0]), "r"(b[1]));
}
__device__ __forceinline__ uint32_t smem_u32(const void* p) {
    uint32_t a;
    asm("{ .reg .u64 t; cvta.to.shared.u64 t, %1; cvt.u32.u64 %0, t; }" : "=r"(a) : "l"(p));
    return a;
}
__device__ __forceinline__ size_t xf_off(int k, int n, int parity) {
    int cc = k >> 7;
    int ccp = (cc < 8) ? cc : (cc + parity * 8);
    int c8 = (k >> 3) & 15;
    int nt = n >> 3;
    int ln = ((n & 7) << 2) | (k & 3);
    int q  = (k >> 2) & 1;
    return ((size_t)(ccp * 16 + c8) * 4 + nt) * 64 + (size_t)ln * 2 + q;
}

#define MB_WAIT(mbar, par) do { uint32_t _d; \
    do { asm volatile("{\n\t.reg .pred p;\n\t" \
        "mbarrier.try_wait.parity.acquire.cta.shared::cta.b64 p, [%1], %2;\n\t" \
        "selp.b32 %0, 1, 0, p;\n\t}" \
        : "=r"(_d) : "r"(mbar), "r"((uint32_t)(par)) : "memory"); } while (!_d); } while (0)

// ---------------- tf32 tensor-core GEMM (prologue M2 / E only) ----------------
__global__ __launch_bounds__(256, 2) void mma_gemm(
    const float* __restrict__ A, const float* __restrict__ Bsrc,
    float* __restrict__ C, int M, int N, int K, int ldb,
    const int* __restrict__ gatherIdx, const float* __restrict__ gatherTab,
    const float* __restrict__ bias, int mode)
{
    __shared__ float As[16][128 + PADW];
    __shared__ float Bs[16][128 + PADW];
    int tid = threadIdx.x;
    int n0 = blockIdx.x * 128, m0 = blockIdx.y * 128;
    int warp = tid >> 5, lane = tid & 31;
    int wm = warp >> 1, wn = warp & 1;
    int grp = lane >> 2, tg = lane & 3;

    float acc[2][8][4] = {};

    const float* arow[2];
    int ac4[2];
    #pragma unroll
    for (int it = 0; it < 2; it++) {
        int idx = tid + it * 256;
        int r = idx >> 2; ac4[it] = (idx & 3) * 4;
        arow[it] = gatherIdx ? (gatherTab + (size_t)gatherIdx[m0 + r] * K)
                             : (A + (size_t)(m0 + r) * K);
    }

    for (int k0 = 0; k0 < K; k0 += 16) {
        #pragma unroll
        for (int it = 0; it < 2; it++) {
            int idx = tid + it * 256;
            int r = idx >> 2;
            float4 v = *(const float4*)(arow[it] + k0 + ac4[it]);
            As[ac4[it]+0][r] = f2tf32(v.x); As[ac4[it]+1][r] = f2tf32(v.y);
            As[ac4[it]+2][r] = f2tf32(v.z); As[ac4[it]+3][r] = f2tf32(v.w);
        }
        if (mode == 2) {
            #pragma unroll
            for (int it = 0; it < 2; it++) {
                int idx = tid + it * 256;
                int r = idx >> 5, c4 = (idx & 31) * 4;
                float4 v = *(const float4*)(Bsrc + (size_t)(k0 + r) * ldb + n0 + c4);
                Bs[r][c4+0] = f2tf32(v.x); Bs[r][c4+1] = f2tf32(v.y);
                Bs[r][c4+2] = f2tf32(v.z); Bs[r][c4+3] = f2tf32(v.w);
            }
        } else {
            #pragma unroll
            for (int it = 0; it < 2; it++) {
                int idx = tid + it * 256;
                int r = idx >> 2, c4 = (idx & 3) * 4;
                float4 v = *(const float4*)(Bsrc + (size_t)(n0 + r) * ldb + k0 + c4);
                Bs[c4+0][r] = f2tf32(v.x); Bs[c4+1][r] = f2tf32(v.y);
                Bs[c4+2][r] = f2tf32(v.z); Bs[c4+3][r] = f2tf32(v.w);
            }
        }
        __syncthreads();

        #pragma unroll
        for (int ks = 0; ks < 2; ks++) {
            int kb = ks * 8;
            uint32_t af[2][4], bf[8][2];
            #pragma unroll
            for (int mt = 0; mt < 2; mt++) {
                int r = wm * 32 + mt * 16 + grp;
                af[mt][0] = __float_as_uint(As[kb+tg  ][r  ]);
                af[mt][1] = __float_as_uint(As[kb+tg  ][r+8]);
                af[mt][2] = __float_as_uint(As[kb+tg+4][r  ]);
                af[mt][3] = __float_as_uint(As[kb+tg+4][r+8]);
            }
            #pragma unroll
            for (int nt = 0; nt < 8; nt++) {
                int cix = wn * 64 + nt * 8 + grp;
                bf[nt][0] = __float_as_uint(Bs[kb+tg  ][cix]);
                bf[nt][1] = __float_as_uint(Bs[kb+tg+4][cix]);
            }
            #pragma unroll
            for (int mt = 0; mt < 2; mt++)
                #pragma unroll
                for (int nt = 0; nt < 8; nt++)
                    mma_op(acc[mt][nt], af[mt], bf[nt]);
        }
        __syncthreads();
    }

    #pragma unroll
    for (int mt = 0; mt < 2; mt++) {
        int mg = m0 + wm * 32 + mt * 16 + grp;
        #pragma unroll
        for (int nt = 0; nt < 8; nt++) {
            int ng = n0 + wn * 64 + nt * 8 + tg * 2;
            float* a4 = acc[mt][nt];
            if (mode == 3) {
                int b1i = mg >> 6,     t1 = mg & 63;
                int b2i = (mg+8) >> 6, t2 = (mg+8) & 63;
                size_t p1 = ((size_t)t1 * RR + ng) * 32 + b1i;
                size_t p2 = ((size_t)t2 * RR + ng) * 32 + b2i;
                C[p1] = a4[0]; C[p1 + 32] = a4[1];
                C[p2] = a4[2]; C[p2 + 32] = a4[3];
            } else {
                *(float2*)(C + (size_t)mg * N + ng)       = make_float2(a4[0], a4[1]);
                *(float2*)(C + (size_t)(mg + 8) * N + ng) = make_float2(a4[2], a4[3]);
            }
        }
    }
}

// ---------------- gate weight fragment pack (unchanged from R8) ----------------
__global__ __launch_bounds__(256) void k_packWF(
    const float* __restrict__ W_ih, const float* __restrict__ W_hh)
{
    int idx = blockIdx.x * 256 + threadIdx.x;
    int lane = idx & 31;
    int mt   = (idx >> 5) & 1;
    int c8   = (idx >> 6) & 15;
    int cc   = (idx >> 10) & 15;
    int blk  = idx >> 14;
    float4 v;
    float* o = (float*)&v;
    #pragma unroll
    for (int q = 0; q < 4; q++) {
        int m = mt * 16 + (lane >> 2) + 8 * (q & 1);
        int g = m >> 3, jo = m & 7;
        int r = g * 1024 + blk * 8 + jo;
        int k = (cc * 16 + c8) * 8 + (lane & 3) + 4 * (q >> 1);
        float wv = (k < 1024) ? W_ih[(size_t)r * 2048 + 1024 + k]
                              : W_hh[(size_t)r * 1024 + (k - 1024)];
        o[q] = f2tf32(wv);
    }
    ((float4*)g_Wf)[idx] = v;
}

// ---------------- W_out fragment pack: [nblk][c8][nt][lane][2] ----------------
__global__ __launch_bounds__(256) void k_packWo(const float* __restrict__ W_out)
{
    size_t idx = (size_t)blockIdx.x * 256 + threadIdx.x;   // float2 id
    int lane = (int)(idx & 31);
    int nt   = (int)((idx >> 5) & 15);
    int c8   = (int)((idx >> 9) & 127);
    int nblk = (int)(idx >> 16);
    int n = nblk * 128 + nt * 8 + (lane >> 2);
    int k = c8 * 8 + (lane & 3);
    float2 v;
    v.x = f2tf32(W_out[(size_t)n * HH + k]);
    v.y = f2tf32(W_out[(size_t)n * HH + k + 4]);
    ((float2*)g_Wo)[idx] = v;
}

// ---------------- no-CCTL global barrier ----------------
__device__ __forceinline__ void gridbar(unsigned target) {
    __syncthreads();
    if (threadIdx.x == 0) {
        unsigned one = 1u, x;
        asm volatile("red.release.gpu.global.add.u32 [%0], %1;"
                     :: "l"(&g_bar), "r"(one) : "memory");
        do {
            asm volatile("ld.acquire.gpu.global.u32 %0, [%1];"
                         : "=r"(x) : "l"(&g_bar));
        } while (x < target);
    }
    __syncthreads();
}

// ---------------- persistent recurrence (R8 + g_Af fragment store) ----------------
__global__ __launch_bounds__(1024, 1) void k_recur(
    const float* __restrict__ memory,
    const float* __restrict__ b_ih, const float* __restrict__ b_hh)
{
    extern __shared__ char smem[];
    float* gate_s = (float*)(smem + OFF_GATE);
    float* p2s    = (float*)(smem + OFF_P2S);
    const uint32_t sbase = smem_u32(smem);
    const uint32_t mb0 = sbase, mb1 = sbase + 8;

    const int tid = threadIdx.x, bid = blockIdx.x;
    const int w = tid >> 5, lane = tid & 31;
    const bool gateblk = (bid < 128);

    if (tid == 0) {
        asm volatile("mbarrier.init.shared.b64 [%0], %1;" :: "r"(mb0), "r"(1u) : "memory");
        asm volatile("mbarrier.init.shared.b64 [%0], %1;" :: "r"(mb1), "r"(1u) : "memory");
    }
    __syncthreads();

    unsigned tgt = NB;

    for (int t = 0; t < TT; t++) {
        // ======== P1: scores ========
        for (int p = bid * 32 + w; p < BB * SS; p += NB * 32) {
            int b = p / SS;
            const float4* m4 = (const float4*)(g_M2 + (size_t)p * HH);
            const float4* h4 = (const float4*)(g_h + b * HH);
            float a = 0.f;
            #pragma unroll
            for (int i = 0; i < 8; i++) {
                float4 mv = m4[i * 32 + lane];
                float4 hv = __ldcg(&h4[i * 32 + lane]);
                a += mv.x*hv.x + mv.y*hv.y + mv.z*hv.z + mv.w*hv.w;
            }
            #pragma unroll
            for (int o = 16; o; o >>= 1) a += __shfl_xor_sync(0xffffffffu, a, o);
            if (!lane) g_scores[p] = a;
        }
        gridbar(tgt); tgt += NB;

        // ======== P2: softmax + ctx -> x fragments ========
        if (gateblk) {
            float* red  = p2s;
            float* swp  = p2s + 256;
            float* part = p2s + 512;
            int b = bid >> 2, jblk = bid & 3;
            float v = -1e30f;
            if (tid < 256) {
                v = (tid < SS) ? __ldcg(&g_scores[b * SS + tid]) : -1e30f;
                red[tid] = v;
            }
            __syncthreads();
            for (int o = 128; o; o >>= 1) { if (tid < o) red[tid] = fmaxf(red[tid], red[tid+o]); __syncthreads(); }
            float mx = red[0]; __syncthreads();
            float e = 0.f;
            if (tid < 256) { e = (tid < SS) ? expf(v - mx) : 0.f; red[tid] = e; }
            __syncthreads();
            for (int o = 128; o; o >>= 1) { if (tid < o) red[tid] += red[tid+o]; __syncthreads(); }
            float inv = 1.f / red[0];
            if (tid < 256) swp[tid] = e * inv;
            __syncthreads();

            int jj = tid & 255, sp = tid >> 8;
            int j = jblk * 256 + jj;
            const float* mp = memory + ((size_t)b * SS + sp * 49) * HH + j;
            float acc = 0.f;
            #pragma unroll 7
            for (int s = 0; s < 49; s++)
                acc += swp[sp * 49 + s] * mp[(size_t)s * HH];
            part[sp * 256 + jj] = acc;
            __syncthreads();
            if (tid < 256) {
                float cv = part[jj] + part[256+jj] + part[512+jj] + part[768+jj];
                g_xf[xf_off(j, b, 0)] = f2tf32(cv);
            }
        }
        gridbar(tgt); tgt += NB;

        // ======== P3: gates pipeline + cell ========
        if (gateblk) {
            if (tid < 256) {
                const int w8 = tid >> 5;
                const int mt = w8 & 1, nt = w8 >> 1;
                const int grp = lane >> 2, tg = lane & 3;
                const int par = t & 1;
                float acc[4] = {0.f, 0.f, 0.f, 0.f};

                auto issue = [&](int cc) {
                    uint32_t mb = (cc & 1) ? mb1 : mb0;
                    uint32_t wd = sbase + OFF_W + (cc & 1) * 16384;
                    uint32_t xd = sbase + OFF_X + (cc & 1) * 16384;
                    const float* ws = g_Wf + ((size_t)bid * 16 + cc) * 4096;
                    int ccp = (cc < 8) ? cc : (cc + par * 8);
                    const float* xs = g_xf + (size_t)ccp * 4096;
                    asm volatile("mbarrier.arrive.expect_tx.shared.b64 _, [%0], %1;"
                                 :: "r"(mb), "r"(32768u) : "memory");
                    asm volatile("cp.async.bulk.shared::cta.global.mbarrier::complete_tx::bytes "
                                 "[%0], [%1], %2, [%3];"
                                 :: "r"(wd), "l"(ws), "r"(16384u), "r"(mb) : "memory");
                    asm volatile("cp.async.bulk.shared::cta.global.mbarrier::complete_tx::bytes "
                                 "[%0], [%1], %2, [%3];"
                                 :: "r"(xd), "l"(xs), "r"(16384u), "r"(mb) : "memory");
                };

                if (tid == 0) { issue(0); issue(1); }

                #pragma unroll
                for (int i = 0; i < 16; i++) {
                    uint32_t mb = (i & 1) ? mb1 : mb0;
                    MB_WAIT(mb, (i >> 1) & 1);
                    const float4* wb = (const float4*)(smem + OFF_W + (i & 1) * 16384);
                    const float2* xb = (const float2*)(smem + OFF_X + (i & 1) * 16384);
                    #pragma unroll
                    for (int c8 = 0; c8 < 16; c8++) {
                        float4 a4 = wb[(c8 * 2 + mt) * 32 + lane];
                        float2 b2 = xb[(c8 * 4 + nt) * 32 + lane];
                        mma_op(acc, (const uint32_t*)&a4, (const uint32_t*)&b2);
                    }
                    asm volatile("bar.sync 7, 256;" ::: "memory");
                    if (tid == 0 && i < 14) issue(i + 2);
                }

                *(float2*)&gate_s[(mt*16 + grp    ) * 32 + nt*8 + tg*2] = make_float2(acc[0], acc[1]);
                *(float2*)&gate_s[(mt*16 + grp + 8) * 32 + nt*8 + tg*2] = make_float2(acc[2], acc[3]);
            }
            __syncthreads();
            if (tid < 256) {
                int b = tid & 31, jo = tid >> 5;
                int j = bid * 8 + jo;
                float pre[4];
                #pragma unroll
                for (int g = 0; g < 4; g++) {
                    pre[g] = gate_s[(g*8 + jo) * 32 + b]
                           + __ldg(&g_ET[((size_t)t * RR + g*1024 + j) * 32 + b])
                           + __ldg(&b_ih[g*1024 + j]) + __ldg(&b_hh[g*1024 + j]);
                }
                float ig = 1.f / (1.f + expf(-pre[0]));
                float fg = 1.f / (1.f + expf(-pre[1]));
                float gg = tanhf(pre[2]);
                float og = 1.f / (1.f + expf(-pre[3]));
                int idx = b * HH + j;
                float cn = fg * g_c[idx] + ig * gg;
                float hn = og * tanhf(cn);
                g_c[idx] = cn;
                g_h[idx] = hn;
                g_xf[xf_off(1024 + j, b, (t + 1) & 1)] = f2tf32(hn);
                // logits A fragment store: m = t*32 + b, k = j
                int m = t * 32 + b;
                int mblk = m >> 7, mtile = (m >> 4) & 7;
                int q = ((m >> 3) & 1) + 2 * ((j >> 2) & 1);
                int lnA = ((m & 7) << 2) | (j & 3);
                g_Af[((((size_t)mblk * 128 + (j >> 3)) * 8 + mtile) * 32 + lnA) * 4 + q]
                    = f2tf32(hn);
            }
        }
        gridbar(tgt); tgt += NB;
    }
}

// ---------------- pipelined logits GEMM ----------------
// A: g_Af [mblk][c8][mt][lane][4] ; B: g_Wo [nblk][c8][nt][lane][2]
// C: out[(b*T + t)*V + n] + bias, with m = t*32 + b
__global__ __launch_bounds__(256, 2) void k_logits(
    const float* __restrict__ bias, float* __restrict__ out)
{
    extern __shared__ char smem[];
    const uint32_t sbase = smem_u32(smem);
    const int tid = threadIdx.x;
    const int mblk = blockIdx.x, nblk = blockIdx.y;
    const int warp = tid >> 5, lane = tid & 31;
    const int wm = warp >> 1, wn = warp & 1;
    const int grp = lane >> 2, tg = lane & 3;

    if (tid == 0) {
        #pragma unroll
        for (int i = 0; i < 3; i++)
            asm volatile("mbarrier.init.shared.b64 [%0], %1;"
                         :: "r"(sbase + i * 8), "r"(1u) : "memory");
    }
    __syncthreads();

    float acc[2][8][4] = {};

    auto issue = [&](int s) {
        int buf = s % 3;
        uint32_t mb = sbase + buf * 8;
        uint32_t ad = sbase + 128 + buf * 32768;
        uint32_t bd = ad + 16384;
        const float* as = g_Af + ((size_t)mblk * 128 + s * 4) * 1024;
        const float* bs = g_Wo + ((size_t)nblk * 128 + s * 4) * 1024;
        asm volatile("mbarrier.arrive.expect_tx.shared.b64 _, [%0], %1;"
                     :: "r"(mb), "r"(32768u) : "memory");
        asm volatile("cp.async.bulk.shared::cta.global.mbarrier::complete_tx::bytes "
                     "[%0], [%1], %2, [%3];"
                     :: "r"(ad), "l"(as), "r"(16384u), "r"(mb) : "memory");
        asm volatile("cp.async.bulk.shared::cta.global.mbarrier::complete_tx::bytes "
                     "[%0], [%1], %2, [%3];"
                     :: "r"(bd), "l"(bs), "r"(16384u), "r"(mb) : "memory");
    };

    if (tid == 0) { issue(0); issue(1); }

    for (int s = 0; s < 32; s++) {
        int buf = s % 3;
        MB_WAIT(sbase + buf * 8, (s / 3) & 1);
        const float4* Ab = (const float4*)(smem + 128 + buf * 32768);
        const float2* Bb = (const float2*)(smem + 128 + buf * 32768 + 16384);
        #pragma unroll
        for (int c8 = 0; c8 < 4; c8++) {
            float4 a0 = Ab[(c8 * 8 + wm * 2 + 0) * 32 + lane];
            float4 a1 = Ab[(c8 * 8 + wm * 2 + 1) * 32 + lane];
            #pragma unroll
            for (int nt = 0; nt < 8; nt++) {
                float2 b2 = Bb[(c8 * 16 + wn * 8 + nt) * 32 + lane];
                mma_op(acc[0][nt], (const uint32_t*)&a0, (const uint32_t*)&b2);
                mma_op(acc[1][nt], (const uint32_t*)&a1, (const uint32_t*)&b2);
            }
        }
        __syncthreads();
        if (tid == 0 && s + 2 < 32) issue(s + 2);
    }

    #pragma unroll
    for (int mt = 0; mt < 2; mt++) {
        int m0 = mblk * 128 + (wm * 2 + mt) * 16 + grp;
        #pragma unroll
        for (int nt = 0; nt < 8; nt++) {
            int ng = nblk * 128 + wn * 64 + nt * 8 + tg * 2;
            float b0 = __ldg(bias + ng), b1 = __ldg(bias + ng + 1);
            int m2 = m0 + 8;
            size_t r1 = ((size_t)(m0 & 31) * TT + (m0 >> 5)) * VV;
            size_t r2 = ((size_t)(m2 & 31) * TT + (m2 >> 5)) * VV;
            *(float2*)(out + r1 + ng) = make_float2(acc[mt][nt][0] + b0, acc[mt][nt][1] + b1);
            *(float2*)(out + r2 + ng) = make_float2(acc[mt][nt][2] + b0, acc[mt][nt][3] + b1);
        }
    }
}

// ---------------- small kernels ----------------
__global__ void k_zero() {
    int i = blockIdx.x * 1024 + threadIdx.x;
    g_h[i] = 0.f; g_c[i] = 0.f;
    g_xf[i] = 0.f; g_xf[i + 32768] = 0.f; g_xf[i + 65536] = 0.f;
    if (i == 0) g_bar = 0u;
}

__global__ void k_copy_hc(float* __restrict__ out) {
    int i = blockIdx.x * 512 + threadIdx.x;
    const size_t OFF = (size_t)BB * TT * VV;
    out[OFF + i] = g_h[i];
    out[OFF + (size_t)BB*HH + i] = g_c[i];
}

// ---------------- launch ----------------
extern "C" void kernel_launch(void* const* d_in, const int* in_sizes, int n_in,
                              void* d_out, int out_size)
{
    const float* memory  = (const float*)d_in[0];
    const int*   captions= (const int*  )d_in[1];
    const float* emb     = (const float*)d_in[2];
    const float* attn_W  = (const float*)d_in[3];
    const float* W_ih    = (const float*)d_in[4];
    const float* W_hh    = (const float*)d_in[5];
    const float* b_ih    = (const float*)d_in[6];
    const float* b_hh    = (const float*)d_in[7];
    const float* W_out   = (const float*)d_in[8];
    const float* b_out   = (const float*)d_in[9];
    float* out = (float*)d_out;

    static float *pM2 = nullptr, *pET = nullptr;
    if (!pM2) {
        cudaGetSymbolAddress((void**)&pM2, g_M2);
        cudaGetSymbolAddress((void**)&pET, g_ET);
        cudaFuncSetAttribute(k_recur,  cudaFuncAttributeMaxDynamicSharedMemorySize, SMEM_RECUR);
        cudaFuncSetAttribute(k_logits, cudaFuncAttributeMaxDynamicSharedMemorySize, SMEM_LOG);
    }

    k_zero<<<32, 1024>>>();

    // M2 = memory @ attn_W
    mma_gemm<<<dim3(HH/128, (BB*SS)/128), 256>>>(
        memory, attn_W, pM2, BB*SS, HH, HH, HH,
        nullptr, nullptr, nullptr, 2);

    // E^T = (emb[captions] @ W_ih[:, :H]^T) transposed to [t][r][b]
    mma_gemm<<<dim3(RR/128, (BB*TT)/128), 256>>>(
        nullptr, W_ih, pET, BB*TT, RR, HH, 2048,
        captions, emb, nullptr, 3);

    // fragment packs
    k_packWF<<<8192, 256>>>(W_ih, W_hh);
    k_packWo<<<64000, 256>>>(W_out);

    // whole recurrence (writes logits A fragments)
    k_recur<<<NB, 1024, SMEM_RECUR>>>(memory, b_ih, b_hh);

    // pipelined logits GEMM
    k_logits<<<dim3(16, 250), 256, SMEM_LOG>>>(b_out, out);

    k_copy_hc<<<64, 512>>>(out);
}